// round 5
// baseline (speedup 1.0000x reference)
#include <cuda_runtime.h>
#include <math.h>

// ---------------- problem constants ----------------
#define NN 50000
#define EE 800000
#define IND 256
#define HD 128      // hidden = out = heads*c1 = 128
#define NHEADS 8
#define C1 16

// ---------------- scratch (static device memory; no allocs) ----------------
// __align__(16): these are accessed with float4 (LDG.128) which traps on <16B alignment.
__device__ __align__(16) float g_h0[NN * HD];        // leaky(x@W_in+b_in)  (pre-BN)
__device__ __align__(16) float g_t1[NN * HD];        // h_norm @ W1 (BN folded)
__device__ __align__(16) float g_out1[NN * HD];      // conv1 out (leaky(agg+bias1)) == skip
__device__ __align__(16) float g_t2[NN * HD];        // out1 @ W2
__device__ __align__(16) float g_conv2[NN * HD];     // conv2 agg + bias2
__device__ __align__(16) float g_h2[NN * HD];        // conv2 + skip@W_skip + b_skip (pre-BN2)
__device__ __align__(16) float g_alpha1[(size_t)EE * NHEADS];
__device__ __align__(16) float g_alpha2[EE];
__device__ __align__(16) float g_as1[NN * NHEADS], g_ad1[NN * NHEADS];
__device__ __align__(16) float g_as2[NN], g_ad2[NN];
__device__ __align__(16) int   g_cnt[NN];
__device__ __align__(16) int   g_rowptr[NN + 1];
__device__ __align__(16) int   g_cursor[NN];
__device__ __align__(16) int   g_csrc[EE];
__device__ __align__(16) float g_bnsum1[HD], g_bnsq1[HD], g_bnsum2[HD], g_bnsq2[HD];
__device__ __align__(16) float g_scale1[HD], g_shift1[HD];
__device__ __align__(16) float g_W1p[HD * HD], g_c1[HD];
__device__ __align__(16) float g_s2[HD], g_sh2[HD];
__device__ int g_is64;   // 1 if edge_index buffer is int64, 0 if int32

__device__ __forceinline__ float lrelu(float v) { return v >= 0.f ? v : 0.2f * v; }

// Decode edge index robustly against harness dtype (int64 kept vs downcast to int32).
__device__ __forceinline__ int edge_idx(const void* ei, long long pos) {
    if (g_is64) return (int)((const long long*)ei)[pos];
    return ((const int*)ei)[pos];
}

// ---------------- dtype detection (1 thread, reads 512B — safe either way) ----------------
__global__ void k_detect(const void* ei) {
    const long long* q = (const long long*)ei;
    int ok = 1;
    for (int i = 0; i < 64; i++) {
        long long v = q[i];
        if (v < 0 || v >= NN) { ok = 0; break; }
    }
    // int32 data seen as int64 = lo + hi*2^32 with hi in [0,NN): out of range with
    // overwhelming probability over 64 probes -> ok=0. True int64 -> all in range -> ok=1.
    g_is64 = ok;
}

// ---------------- zero scratch that needs zeroing each call ----------------
__global__ void k_zero() {
    int i = blockIdx.x * blockDim.x + threadIdx.x;
    if (i < NN) g_cnt[i] = 0;
    if (i < HD) { g_bnsum1[i] = 0.f; g_bnsq1[i] = 0.f; g_bnsum2[i] = 0.f; g_bnsq2[i] = 0.f; }
}

// ---------------- CSR build ----------------
__global__ void k_count(const void* __restrict__ ei) {
    int e = blockIdx.x * blockDim.x + threadIdx.x;
    if (e < EE) {
        int d = edge_idx(ei, (long long)EE + e);
        if (d >= 0 && d < NN) atomicAdd(&g_cnt[d], 1);
    }
}

__global__ void k_scan() {
    __shared__ int sh[1024];
    __shared__ int carry;
    int tid = threadIdx.x;
    if (tid == 0) carry = 0;
    __syncthreads();
    for (int base = 0; base < NN; base += 1024) {
        int v = (base + tid < NN) ? g_cnt[base + tid] : 0;
        sh[tid] = v;
        __syncthreads();
        for (int off = 1; off < 1024; off <<= 1) {
            int t = (tid >= off) ? sh[tid - off] : 0;
            __syncthreads();
            sh[tid] += t;
            __syncthreads();
        }
        int excl = sh[tid] - v;
        int c = carry;
        if (base + tid < NN) { g_rowptr[base + tid] = c + excl; g_cursor[base + tid] = c + excl; }
        int tot = sh[1023];
        __syncthreads();
        if (tid == 0) carry = c + tot;
        __syncthreads();
    }
    if (tid == 0) g_rowptr[NN] = carry;
}

__global__ void k_fill(const void* __restrict__ ei) {
    int e = blockIdx.x * blockDim.x + threadIdx.x;
    if (e < EE) {
        int s = edge_idx(ei, e);
        int d = edge_idx(ei, (long long)EE + e);
        if (d >= 0 && d < NN && s >= 0 && s < NN) {
            int p = atomicAdd(&g_cursor[d], 1);
            if (p >= 0 && p < EE) g_csrc[p] = s;
        }
    }
}

// ---------------- generic tiled fp32 GEMM: C[M=NN, 128] = A[NN,K] @ B[K,128] ----------------
template <int K, bool LEAKY, bool ADDM, bool STATS>
__global__ void k_gemm(const float* __restrict__ A, const float* __restrict__ B,
                       float* __restrict__ C, const float* __restrict__ bias,
                       const float* __restrict__ addm,
                       float* __restrict__ bnsum, float* __restrict__ bnsq) {
    __shared__ float As[16][65];   // padded: conflict-free transposed stores
    __shared__ float Bs[16][64];
    __shared__ float s_sum[64], s_sq[64];
    const int tid = threadIdx.x;
    const int m0 = blockIdx.x * 64;
    const int n0 = blockIdx.y * 64;
    if (STATS && tid < 64) { s_sum[tid] = 0.f; s_sq[tid] = 0.f; }
    const int tr = tid >> 4, tc = tid & 15;
    const int ar = tid >> 2;          // A row within tile
    const int ak = (tid & 3) * 4;     // A k-offset within tile
    const int br = tid >> 4;          // B row within tile
    const int bc = (tid & 15) * 4;    // B col within tile
    float c[4][4] = {};

    for (int k0 = 0; k0 < K; k0 += 16) {
        float4 av;
        int grow = m0 + ar;
        if (grow < NN) av = *reinterpret_cast<const float4*>(A + (size_t)grow * K + k0 + ak);
        else           av = make_float4(0.f, 0.f, 0.f, 0.f);
        As[ak + 0][ar] = av.x; As[ak + 1][ar] = av.y;
        As[ak + 2][ar] = av.z; As[ak + 3][ar] = av.w;
        *reinterpret_cast<float4*>(&Bs[br][bc]) =
            *reinterpret_cast<const float4*>(B + (size_t)(k0 + br) * HD + n0 + bc);
        __syncthreads();
#pragma unroll
        for (int kk = 0; kk < 16; kk++) {
            float a0 = As[kk][tr * 4 + 0], a1 = As[kk][tr * 4 + 1];
            float a2 = As[kk][tr * 4 + 2], a3 = As[kk][tr * 4 + 3];
            float4 b4 = *reinterpret_cast<const float4*>(&Bs[kk][tc * 4]);
            c[0][0] += a0 * b4.x; c[0][1] += a0 * b4.y; c[0][2] += a0 * b4.z; c[0][3] += a0 * b4.w;
            c[1][0] += a1 * b4.x; c[1][1] += a1 * b4.y; c[1][2] += a1 * b4.z; c[1][3] += a1 * b4.w;
            c[2][0] += a2 * b4.x; c[2][1] += a2 * b4.y; c[2][2] += a2 * b4.z; c[2][3] += a2 * b4.w;
            c[3][0] += a3 * b4.x; c[3][1] += a3 * b4.y; c[3][2] += a3 * b4.z; c[3][3] += a3 * b4.w;
        }
        __syncthreads();
    }

    float lsum[4] = {0.f, 0.f, 0.f, 0.f}, lsq[4] = {0.f, 0.f, 0.f, 0.f};
#pragma unroll
    for (int i = 0; i < 4; i++) {
        int m = m0 + tr * 4 + i;
        if (m < NN) {
#pragma unroll
            for (int j = 0; j < 4; j++) {
                int n = n0 + tc * 4 + j;
                float v = c[i][j];
                if (bias) v += bias[n];
                if (ADDM) v += addm[(size_t)m * HD + n];
                if (LEAKY) v = lrelu(v);
                C[(size_t)m * HD + n] = v;
                if (STATS) { lsum[j] += v; lsq[j] += v * v; }
            }
        }
    }
    if (STATS) {
#pragma unroll
        for (int j = 0; j < 4; j++) {
            atomicAdd(&s_sum[tc * 4 + j], lsum[j]);
            atomicAdd(&s_sq[tc * 4 + j], lsq[j]);
        }
        __syncthreads();
        if (tid < 64) {
            atomicAdd(&bnsum[n0 + tid], s_sum[tid]);
            atomicAdd(&bnsq[n0 + tid], s_sq[tid]);
        }
    }
}

// ---------------- BN1 prep: fold BN into W1 ----------------
__global__ void k_bnprep1(const float* __restrict__ gamma1, const float* __restrict__ beta1,
                          const float* __restrict__ W1) {
    int c = threadIdx.x;  // 128 threads
    float mean = g_bnsum1[c] / (float)NN;
    float var = g_bnsq1[c] / (float)NN - mean * mean;
    float sc = gamma1[c] * rsqrtf(var + 1e-5f);
    float sh = beta1[c] - mean * sc;
    g_scale1[c] = sc;
    g_shift1[c] = sh;
    __syncthreads();
    float cj = 0.f;
    for (int k = 0; k < HD; k++) {
        cj += g_shift1[k] * W1[k * HD + c];
        g_W1p[k * HD + c] = g_scale1[k] * W1[k * HD + c];
    }
    g_c1[c] = cj;
}

__global__ void k_bnprep2(const float* __restrict__ gamma2, const float* __restrict__ beta2) {
    int c = threadIdx.x;
    float mean = g_bnsum2[c] / (float)NN;
    float var = g_bnsq2[c] / (float)NN - mean * mean;
    float sc = gamma2[c] * rsqrtf(var + 1e-5f);
    g_s2[c] = sc;
    g_sh2[c] = beta2[c] - mean * sc;
}

// ---------------- attention coefficients ----------------
__global__ void k_att1(const float* __restrict__ att_src, const float* __restrict__ att_dst) {
    int gt = blockIdx.x * blockDim.x + threadIdx.x;
    int w = gt >> 5, lane = gt & 31;
    if (w >= NN) return;
    float4 t4 = *reinterpret_cast<const float4*>(g_t1 + (size_t)w * HD + lane * 4);
    float4 s4 = *reinterpret_cast<const float4*>(att_src + lane * 4);
    float4 d4 = *reinterpret_cast<const float4*>(att_dst + lane * 4);
    float ps = t4.x * s4.x + t4.y * s4.y + t4.z * s4.z + t4.w * s4.w;
    float pd = t4.x * d4.x + t4.y * d4.y + t4.z * d4.z + t4.w * d4.w;
    ps += __shfl_xor_sync(0xFFFFFFFFu, ps, 1); ps += __shfl_xor_sync(0xFFFFFFFFu, ps, 2);
    pd += __shfl_xor_sync(0xFFFFFFFFu, pd, 1); pd += __shfl_xor_sync(0xFFFFFFFFu, pd, 2);
    if ((lane & 3) == 0) {
        g_as1[w * NHEADS + (lane >> 2)] = ps;
        g_ad1[w * NHEADS + (lane >> 2)] = pd;
    }
}

__global__ void k_att2(const float* __restrict__ att_src, const float* __restrict__ att_dst) {
    int gt = blockIdx.x * blockDim.x + threadIdx.x;
    int w = gt >> 5, lane = gt & 31;
    if (w >= NN) return;
    float4 t4 = *reinterpret_cast<const float4*>(g_t2 + (size_t)w * HD + lane * 4);
    float4 s4 = *reinterpret_cast<const float4*>(att_src + lane * 4);
    float4 d4 = *reinterpret_cast<const float4*>(att_dst + lane * 4);
    float ps = t4.x * s4.x + t4.y * s4.y + t4.z * s4.z + t4.w * s4.w;
    float pd = t4.x * d4.x + t4.y * d4.y + t4.z * d4.z + t4.w * d4.w;
#pragma unroll
    for (int off = 16; off; off >>= 1) {
        ps += __shfl_xor_sync(0xFFFFFFFFu, ps, off);
        pd += __shfl_xor_sync(0xFFFFFFFFu, pd, off);
    }
    if (lane == 0) { g_as2[w] = ps; g_ad2[w] = pd; }
}

// ---------------- softmax per dst (writes alpha in CSR order) ----------------
__global__ void k_softmax1() {
    int gt = blockIdx.x * blockDim.x + threadIdx.x;
    int w = gt >> 5, lane = gt & 31;
    if (w >= NN) return;
    int beg = g_rowptr[w], end = g_rowptr[w + 1];
    if (beg == end) return;
    int h = lane & 7, es = lane >> 3;  // 4 edges in parallel x 8 heads
    float ad = g_ad1[w * NHEADS + h];
    float mx = -INFINITY;
    for (int j = beg + es; j < end; j += 4) {
        int s = g_csrc[j];
        float v = lrelu(g_as1[s * NHEADS + h] + ad);
        mx = fmaxf(mx, v);
    }
    mx = fmaxf(mx, __shfl_xor_sync(0xFFFFFFFFu, mx, 8));
    mx = fmaxf(mx, __shfl_xor_sync(0xFFFFFFFFu, mx, 16));
    float den = 0.f;
    for (int j = beg + es; j < end; j += 4) {
        int s = g_csrc[j];
        float v = lrelu(g_as1[s * NHEADS + h] + ad);
        den += __expf(v - mx);
    }
    den += __shfl_xor_sync(0xFFFFFFFFu, den, 8);
    den += __shfl_xor_sync(0xFFFFFFFFu, den, 16);
    float inv = 1.f / fmaxf(den, 1e-16f);
    for (int j = beg + es; j < end; j += 4) {
        int s = g_csrc[j];
        float v = lrelu(g_as1[s * NHEADS + h] + ad);
        g_alpha1[(size_t)j * NHEADS + h] = __expf(v - mx) * inv;
    }
}

__global__ void k_softmax2() {
    int gt = blockIdx.x * blockDim.x + threadIdx.x;
    int w = gt >> 5, lane = gt & 31;
    if (w >= NN) return;
    int beg = g_rowptr[w], end = g_rowptr[w + 1];
    if (beg == end) return;
    float ad = g_ad2[w];
    float mx = -INFINITY;
    for (int j = beg + lane; j < end; j += 32) {
        float v = lrelu(g_as2[g_csrc[j]] + ad);
        mx = fmaxf(mx, v);
    }
#pragma unroll
    for (int off = 16; off; off >>= 1) mx = fmaxf(mx, __shfl_xor_sync(0xFFFFFFFFu, mx, off));
    float den = 0.f;
    for (int j = beg + lane; j < end; j += 32) {
        float v = lrelu(g_as2[g_csrc[j]] + ad);
        den += __expf(v - mx);
    }
#pragma unroll
    for (int off = 16; off; off >>= 1) den += __shfl_xor_sync(0xFFFFFFFFu, den, off);
    float inv = 1.f / fmaxf(den, 1e-16f);
    for (int j = beg + lane; j < end; j += 32) {
        float v = lrelu(g_as2[g_csrc[j]] + ad);
        g_alpha2[j] = __expf(v - mx) * inv;
    }
}

// ---------------- aggregation (warp per dst node, gather from L2) ----------------
__global__ void k_agg1(const float* __restrict__ bias1) {
    int gt = blockIdx.x * blockDim.x + threadIdx.x;
    int w = gt >> 5, lane = gt & 31;
    if (w >= NN) return;
    int beg = g_rowptr[w], end = g_rowptr[w + 1];
    int hh = lane >> 2;  // head for this lane's 4 columns
    float ax = 0.f, ay = 0.f, az = 0.f, aw = 0.f;
#pragma unroll 2
    for (int j = beg; j < end; j++) {
        int s = g_csrc[j];
        float a = g_alpha1[(size_t)j * NHEADS + hh];
        float4 t4 = *reinterpret_cast<const float4*>(g_t1 + (size_t)s * HD + lane * 4);
        ax += a * t4.x; ay += a * t4.y; az += a * t4.z; aw += a * t4.w;
    }
    float4 b4 = *reinterpret_cast<const float4*>(bias1 + lane * 4);
    float4 o;
    o.x = lrelu(ax + b4.x); o.y = lrelu(ay + b4.y);
    o.z = lrelu(az + b4.z); o.w = lrelu(aw + b4.w);
    *reinterpret_cast<float4*>(g_out1 + (size_t)w * HD + lane * 4) = o;
}

__global__ void k_agg2(const float* __restrict__ bias2) {
    int gt = blockIdx.x * blockDim.x + threadIdx.x;
    int w = gt >> 5, lane = gt & 31;
    if (w >= NN) return;
    int beg = g_rowptr[w], end = g_rowptr[w + 1];
    float ax = 0.f, ay = 0.f, az = 0.f, aw = 0.f;
#pragma unroll 2
    for (int j = beg; j < end; j++) {
        int s = g_csrc[j];
        float a = g_alpha2[j];
        float4 t4 = *reinterpret_cast<const float4*>(g_t2 + (size_t)s * HD + lane * 4);
        ax += a * t4.x; ay += a * t4.y; az += a * t4.z; aw += a * t4.w;
    }
    float4 b4 = *reinterpret_cast<const float4*>(bias2 + lane * 4);
    float4 o = make_float4(ax + b4.x, ay + b4.y, az + b4.z, aw + b4.w);
    *reinterpret_cast<float4*>(g_conv2 + (size_t)w * HD + lane * 4) = o;
}

// ---------------- final: BN2 apply + row L2 normalize ----------------
__global__ void k_final(float* __restrict__ out) {
    int gt = blockIdx.x * blockDim.x + threadIdx.x;
    int w = gt >> 5, lane = gt & 31;
    if (w >= NN) return;
    float4 h4 = *reinterpret_cast<const float4*>(g_h2 + (size_t)w * HD + lane * 4);
    float4 s4 = *reinterpret_cast<const float4*>(g_s2 + lane * 4);
    float4 sh4 = *reinterpret_cast<const float4*>(g_sh2 + lane * 4);
    float4 y;
    y.x = h4.x * s4.x + sh4.x; y.y = h4.y * s4.y + sh4.y;
    y.z = h4.z * s4.z + sh4.z; y.w = h4.w * s4.w + sh4.w;
    float ss = y.x * y.x + y.y * y.y + y.z * y.z + y.w * y.w;
#pragma unroll
    for (int off = 16; off; off >>= 1) ss += __shfl_xor_sync(0xFFFFFFFFu, ss, off);
    float inv = 1.f / fmaxf(sqrtf(ss), 1e-12f);
    y.x *= inv; y.y *= inv; y.z *= inv; y.w *= inv;
    *reinterpret_cast<float4*>(out + (size_t)w * HD + lane * 4) = y;
}

// ---------------- host launcher ----------------
extern "C" void kernel_launch(void* const* d_in, const int* in_sizes, int n_in,
                              void* d_out, int out_size) {
    const float* x        = (const float*)d_in[0];
    const float* W_in     = (const float*)d_in[1];
    const float* b_in     = (const float*)d_in[2];
    const float* gamma1   = (const float*)d_in[3];
    const float* beta1    = (const float*)d_in[4];
    const float* W1       = (const float*)d_in[5];
    const float* att_src1 = (const float*)d_in[6];
    const float* att_dst1 = (const float*)d_in[7];
    const float* bias1    = (const float*)d_in[8];
    const float* W2       = (const float*)d_in[9];
    const float* att_src2 = (const float*)d_in[10];
    const float* att_dst2 = (const float*)d_in[11];
    const float* bias2    = (const float*)d_in[12];
    const float* W_skip   = (const float*)d_in[13];
    const float* b_skip   = (const float*)d_in[14];
    const float* gamma2   = (const float*)d_in[15];
    const float* beta2    = (const float*)d_in[16];
    const void*  ei       = (const void*)d_in[17];   // int32 or int64 — detected on device
    float* out = (float*)d_out;

    // symbol addresses for generic-pointer kernels
    float *p_h0, *p_t1, *p_out1, *p_t2, *p_conv2, *p_h2, *p_W1p, *p_c1;
    float *p_bnsum1, *p_bnsq1, *p_bnsum2, *p_bnsq2;
    cudaGetSymbolAddress((void**)&p_h0, g_h0);
    cudaGetSymbolAddress((void**)&p_t1, g_t1);
    cudaGetSymbolAddress((void**)&p_out1, g_out1);
    cudaGetSymbolAddress((void**)&p_t2, g_t2);
    cudaGetSymbolAddress((void**)&p_conv2, g_conv2);
    cudaGetSymbolAddress((void**)&p_h2, g_h2);
    cudaGetSymbolAddress((void**)&p_W1p, g_W1p);
    cudaGetSymbolAddress((void**)&p_c1, g_c1);
    cudaGetSymbolAddress((void**)&p_bnsum1, g_bnsum1);
    cudaGetSymbolAddress((void**)&p_bnsq1, g_bnsq1);
    cudaGetSymbolAddress((void**)&p_bnsum2, g_bnsum2);
    cudaGetSymbolAddress((void**)&p_bnsq2, g_bnsq2);

    const int nb_edge = (EE + 255) / 256;
    const int nb_node = (NN * 32 + 255) / 256;
    const dim3 gemm_grid((NN + 63) / 64, HD / 64);

    k_detect<<<1, 1>>>(ei);
    k_zero<<<(NN + 255) / 256, 256>>>();
    k_count<<<nb_edge, 256>>>(ei);
    k_scan<<<1, 1024>>>();
    k_fill<<<nb_edge, 256>>>(ei);

    // h0 = leaky(x @ W_in + b_in), BN1 stats
    k_gemm<IND, true, false, true><<<gemm_grid, 256>>>(x, W_in, p_h0, b_in, nullptr, p_bnsum1, p_bnsq1);
    k_bnprep1<<<1, HD>>>(gamma1, beta1, W1);
    // t1 = h_norm @ W1  (BN folded into W1p / c1)
    k_gemm<HD, false, false, false><<<gemm_grid, 256>>>(p_h0, p_W1p, p_t1, p_c1, nullptr, nullptr, nullptr);
    k_att1<<<nb_node, 256>>>(att_src1, att_dst1);
    k_softmax1<<<nb_node, 256>>>();
    k_agg1<<<nb_node, 256>>>(bias1);
    // t2 = out1 @ W2
    k_gemm<HD, false, false, false><<<gemm_grid, 256>>>(p_out1, W2, p_t2, nullptr, nullptr, nullptr, nullptr);
    k_att2<<<nb_node, 256>>>(att_src2, att_dst2);
    k_softmax2<<<nb_node, 256>>>();
    k_agg2<<<nb_node, 256>>>(bias2);
    // h2 = conv2 + out1 @ W_skip + b_skip, BN2 stats
    k_gemm<HD, false, true, true><<<gemm_grid, 256>>>(p_out1, W_skip, p_h2, b_skip, p_conv2, p_bnsum2, p_bnsq2);
    k_bnprep2<<<1, HD>>>(gamma2, beta2);
    k_final<<<nb_node, 256>>>(out);
}

// round 6
// speedup vs baseline: 1.0539x; 1.0539x over previous
#include <cuda_runtime.h>
#include <math.h>

// ---------------- problem constants ----------------
#define NN 50000
#define EE 800000
#define IND 256
#define HD 128      // hidden = out = heads*c1 = 128
#define NHEADS 8
#define C1 16
#define SCAN_BLK 256
#define NSCAN ((NN + SCAN_BLK - 1) / SCAN_BLK)   // 196

// ---------------- scratch (static device memory; no allocs) ----------------
__device__ __align__(16) float g_h0[NN * HD];
__device__ __align__(16) float g_t1[NN * HD];
__device__ __align__(16) float g_out1[NN * HD];
__device__ __align__(16) float g_t2[NN * HD];
__device__ __align__(16) float g_conv2[NN * HD];
__device__ __align__(16) float g_h2[NN * HD];
__device__ __align__(16) float g_alpha1[(size_t)EE * NHEADS];
__device__ __align__(16) float g_alpha2[EE];
__device__ __align__(16) float g_as1[NN * NHEADS], g_ad1[NN * NHEADS];
__device__ __align__(16) float g_as2[NN], g_ad2[NN];
__device__ __align__(16) int   g_cnt[NN];
__device__ __align__(16) int   g_scantmp[NN];
__device__ __align__(16) int   g_blksum[SCAN_BLK];
__device__ __align__(16) int   g_blkoff[SCAN_BLK];
__device__ int   g_total;
__device__ __align__(16) int   g_rowptr[NN + 1];
__device__ __align__(16) int   g_cursor[NN];
__device__ __align__(16) int   g_csrc[EE];
__device__ __align__(16) float g_bnsum1[HD], g_bnsq1[HD], g_bnsum2[HD], g_bnsq2[HD];
__device__ __align__(16) float g_scale1[HD], g_shift1[HD];
__device__ __align__(16) float g_W1p[HD * HD], g_c1[HD];
__device__ __align__(16) float g_s2[HD], g_sh2[HD];
__device__ int g_is64;

__device__ __forceinline__ float lrelu(float v) { return v >= 0.f ? v : 0.2f * v; }

__device__ __forceinline__ int edge_idx(const void* ei, long long pos) {
    if (g_is64) return (int)((const long long*)ei)[pos];
    return ((const int*)ei)[pos];
}

// ---------------- dtype detection ----------------
__global__ void k_detect(const void* ei) {
    const long long* q = (const long long*)ei;
    int ok = 1;
    for (int i = 0; i < 64; i++) {
        long long v = q[i];
        if (v < 0 || v >= NN) { ok = 0; break; }
    }
    g_is64 = ok;
}

// ---------------- zero ----------------
__global__ void k_zero() {
    int i = blockIdx.x * blockDim.x + threadIdx.x;
    if (i < NN) g_cnt[i] = 0;
    if (i < HD) { g_bnsum1[i] = 0.f; g_bnsq1[i] = 0.f; g_bnsum2[i] = 0.f; g_bnsq2[i] = 0.f; }
}

// ---------------- CSR build ----------------
__global__ void k_count(const void* __restrict__ ei) {
    int e = blockIdx.x * blockDim.x + threadIdx.x;
    if (e < EE) {
        int d = edge_idx(ei, (long long)EE + e);
        if (d >= 0 && d < NN) atomicAdd(&g_cnt[d], 1);
    }
}

// ---- parallel scan: A) per-block inclusive scan + block sums ----
__global__ void k_scanA() {
    __shared__ int sh[SCAN_BLK];
    int tid = threadIdx.x;
    int i = blockIdx.x * SCAN_BLK + tid;
    int v = (i < NN) ? g_cnt[i] : 0;
    sh[tid] = v;
    __syncthreads();
#pragma unroll
    for (int off = 1; off < SCAN_BLK; off <<= 1) {
        int t = (tid >= off) ? sh[tid - off] : 0;
        __syncthreads();
        sh[tid] += t;
        __syncthreads();
    }
    if (i < NN) g_scantmp[i] = sh[tid];              // inclusive within block
    if (tid == SCAN_BLK - 1) g_blksum[blockIdx.x] = sh[tid];
}

// ---- B) scan the 196 block sums (1 block) ----
__global__ void k_scanB() {
    __shared__ int sh[SCAN_BLK];
    int tid = threadIdx.x;
    int v = (tid < NSCAN) ? g_blksum[tid] : 0;
    sh[tid] = v;
    __syncthreads();
#pragma unroll
    for (int off = 1; off < SCAN_BLK; off <<= 1) {
        int t = (tid >= off) ? sh[tid - off] : 0;
        __syncthreads();
        sh[tid] += t;
        __syncthreads();
    }
    g_blkoff[tid] = sh[tid] - v;                      // exclusive
    if (tid == SCAN_BLK - 1) g_total = sh[tid];
}

// ---- C) rowptr[i] = blkoff + (inclusive - own) ----
__global__ void k_scanC() {
    int i = blockIdx.x * blockDim.x + threadIdx.x;
    if (i < NN) {
        int r = g_blkoff[blockIdx.x * blockDim.x / SCAN_BLK + (threadIdx.x / SCAN_BLK)];
        // blockDim == SCAN_BLK so simplify:
        r = g_blkoff[blockIdx.x] + g_scantmp[i] - g_cnt[i];
        g_rowptr[i] = r;
        g_cursor[i] = r;
    }
    if (i == 0) g_rowptr[NN] = g_total;
}

__global__ void k_fill(const void* __restrict__ ei) {
    int e = blockIdx.x * blockDim.x + threadIdx.x;
    if (e < EE) {
        int s = edge_idx(ei, e);
        int d = edge_idx(ei, (long long)EE + e);
        if (d >= 0 && d < NN && s >= 0 && s < NN) {
            int p = atomicAdd(&g_cursor[d], 1);
            if (p >= 0 && p < EE) g_csrc[p] = s;
        }
    }
}

// ---------------- fp32 GEMM: C[NN,128] = A[NN,K] @ B[K,128], 128x128 tile, 8x8/thread ----
template <int K, bool LEAKY, bool ADDM, bool STATS>
__global__ void __launch_bounds__(256, 2) k_gemm(
        const float* __restrict__ A, const float* __restrict__ B,
        float* __restrict__ C, const float* __restrict__ bias,
        const float* __restrict__ addm,
        float* __restrict__ bnsum, float* __restrict__ bnsq) {
    __shared__ float As[16][136];   // padded to 136 (16B-aligned rows, conflict-free)
    __shared__ float Bs[16][128];
    __shared__ float s_sum[128], s_sq[128];
    const int tid = threadIdx.x;
    const int m0 = blockIdx.x * 128;
    if (STATS && tid < 128) { s_sum[tid] = 0.f; s_sq[tid] = 0.f; }
    const int tr = tid >> 4;          // 0..15 row group (x8)
    const int tc = tid & 15;          // 0..15 col group (x8)
    const int lar = tid >> 1;         // A load row 0..127
    const int lak = (tid & 1) * 8;    // A load k offset 0 or 8
    const int lbr = tid >> 4;         // B load row 0..15
    const int lbc = (tid & 15) * 8;   // B load col
    float acc[8][8] = {};

    for (int k0 = 0; k0 < K; k0 += 16) {
        // A tile (transposed into As[k][m]): each thread 8 floats of one row
        {
            int gr = m0 + lar;
            float4 a0, a1;
            if (gr < NN) {
                const float* ap = A + (size_t)gr * K + k0 + lak;
                a0 = *reinterpret_cast<const float4*>(ap);
                a1 = *reinterpret_cast<const float4*>(ap + 4);
            } else {
                a0 = make_float4(0.f, 0.f, 0.f, 0.f);
                a1 = a0;
            }
            As[lak + 0][lar] = a0.x; As[lak + 1][lar] = a0.y;
            As[lak + 2][lar] = a0.z; As[lak + 3][lar] = a0.w;
            As[lak + 4][lar] = a1.x; As[lak + 5][lar] = a1.y;
            As[lak + 6][lar] = a1.z; As[lak + 7][lar] = a1.w;
        }
        // B tile: 16 rows x 128 cols
        {
            const float* bp = B + (size_t)(k0 + lbr) * HD + lbc;
            *reinterpret_cast<float4*>(&Bs[lbr][lbc])     = *reinterpret_cast<const float4*>(bp);
            *reinterpret_cast<float4*>(&Bs[lbr][lbc + 4]) = *reinterpret_cast<const float4*>(bp + 4);
        }
        __syncthreads();
#pragma unroll
        for (int kk = 0; kk < 16; kk++) {
            float a[8], b[8];
            float4 av0 = *reinterpret_cast<const float4*>(&As[kk][tr * 8]);
            float4 av1 = *reinterpret_cast<const float4*>(&As[kk][tr * 8 + 4]);
            float4 bv0 = *reinterpret_cast<const float4*>(&Bs[kk][tc * 8]);
            float4 bv1 = *reinterpret_cast<const float4*>(&Bs[kk][tc * 8 + 4]);
            a[0]=av0.x; a[1]=av0.y; a[2]=av0.z; a[3]=av0.w;
            a[4]=av1.x; a[5]=av1.y; a[6]=av1.z; a[7]=av1.w;
            b[0]=bv0.x; b[1]=bv0.y; b[2]=bv0.z; b[3]=bv0.w;
            b[4]=bv1.x; b[5]=bv1.y; b[6]=bv1.z; b[7]=bv1.w;
#pragma unroll
            for (int i = 0; i < 8; i++)
#pragma unroll
                for (int j = 0; j < 8; j++)
                    acc[i][j] += a[i] * b[j];
        }
        __syncthreads();
    }

    float lsum[8] = {}, lsq[8] = {};
    float bcol[8];
#pragma unroll
    for (int j = 0; j < 8; j++) bcol[j] = bias ? bias[tc * 8 + j] : 0.f;
#pragma unroll
    for (int i = 0; i < 8; i++) {
        int m = m0 + tr * 8 + i;
        if (m < NN) {
            float4 o0, o1;
            float v[8];
#pragma unroll
            for (int j = 0; j < 8; j++) {
                float t = acc[i][j] + bcol[j];
                if (ADDM) t += addm[(size_t)m * HD + tc * 8 + j];
                if (LEAKY) t = lrelu(t);
                v[j] = t;
                if (STATS) { lsum[j] += t; lsq[j] += t * t; }
            }
            o0 = make_float4(v[0], v[1], v[2], v[3]);
            o1 = make_float4(v[4], v[5], v[6], v[7]);
            float* cp = C + (size_t)m * HD + tc * 8;
            *reinterpret_cast<float4*>(cp)     = o0;
            *reinterpret_cast<float4*>(cp + 4) = o1;
        }
    }
    if (STATS) {
#pragma unroll
        for (int j = 0; j < 8; j++) {
            atomicAdd(&s_sum[tc * 8 + j], lsum[j]);
            atomicAdd(&s_sq[tc * 8 + j], lsq[j]);
        }
        __syncthreads();
        if (tid < 128) {
            atomicAdd(&bnsum[tid], s_sum[tid]);
            atomicAdd(&bnsq[tid], s_sq[tid]);
        }
    }
}

// ---------------- BN preps ----------------
__global__ void k_bnprep1(const float* __restrict__ gamma1, const float* __restrict__ beta1,
                          const float* __restrict__ W1) {
    int c = threadIdx.x;
    float mean = g_bnsum1[c] / (float)NN;
    float var = g_bnsq1[c] / (float)NN - mean * mean;
    float sc = gamma1[c] * rsqrtf(var + 1e-5f);
    float sh = beta1[c] - mean * sc;
    g_scale1[c] = sc;
    g_shift1[c] = sh;
    __syncthreads();
    float cj = 0.f;
    for (int k = 0; k < HD; k++) {
        cj += g_shift1[k] * W1[k * HD + c];
        g_W1p[k * HD + c] = g_scale1[k] * W1[k * HD + c];
    }
    g_c1[c] = cj;
}

__global__ void k_bnprep2(const float* __restrict__ gamma2, const float* __restrict__ beta2) {
    int c = threadIdx.x;
    float mean = g_bnsum2[c] / (float)NN;
    float var = g_bnsq2[c] / (float)NN - mean * mean;
    float sc = gamma2[c] * rsqrtf(var + 1e-5f);
    g_s2[c] = sc;
    g_sh2[c] = beta2[c] - mean * sc;
}

// ---------------- attention coefficients ----------------
__global__ void k_att1(const float* __restrict__ att_src, const float* __restrict__ att_dst) {
    int gt = blockIdx.x * blockDim.x + threadIdx.x;
    int w = gt >> 5, lane = gt & 31;
    if (w >= NN) return;
    float4 t4 = *reinterpret_cast<const float4*>(g_t1 + (size_t)w * HD + lane * 4);
    float4 s4 = *reinterpret_cast<const float4*>(att_src + lane * 4);
    float4 d4 = *reinterpret_cast<const float4*>(att_dst + lane * 4);
    float ps = t4.x * s4.x + t4.y * s4.y + t4.z * s4.z + t4.w * s4.w;
    float pd = t4.x * d4.x + t4.y * d4.y + t4.z * d4.z + t4.w * d4.w;
    ps += __shfl_xor_sync(0xFFFFFFFFu, ps, 1); ps += __shfl_xor_sync(0xFFFFFFFFu, ps, 2);
    pd += __shfl_xor_sync(0xFFFFFFFFu, pd, 1); pd += __shfl_xor_sync(0xFFFFFFFFu, pd, 2);
    if ((lane & 3) == 0) {
        g_as1[w * NHEADS + (lane >> 2)] = ps;
        g_ad1[w * NHEADS + (lane >> 2)] = pd;
    }
}

__global__ void k_att2(const float* __restrict__ att_src, const float* __restrict__ att_dst) {
    int gt = blockIdx.x * blockDim.x + threadIdx.x;
    int w = gt >> 5, lane = gt & 31;
    if (w >= NN) return;
    float4 t4 = *reinterpret_cast<const float4*>(g_t2 + (size_t)w * HD + lane * 4);
    float4 s4 = *reinterpret_cast<const float4*>(att_src + lane * 4);
    float4 d4 = *reinterpret_cast<const float4*>(att_dst + lane * 4);
    float ps = t4.x * s4.x + t4.y * s4.y + t4.z * s4.z + t4.w * s4.w;
    float pd = t4.x * d4.x + t4.y * d4.y + t4.z * d4.z + t4.w * d4.w;
#pragma unroll
    for (int off = 16; off; off >>= 1) {
        ps += __shfl_xor_sync(0xFFFFFFFFu, ps, off);
        pd += __shfl_xor_sync(0xFFFFFFFFu, pd, off);
    }
    if (lane == 0) { g_as2[w] = ps; g_ad2[w] = pd; }
}

// ---------------- softmax per dst ----------------
__global__ void k_softmax1() {
    int gt = blockIdx.x * blockDim.x + threadIdx.x;
    int w = gt >> 5, lane = gt & 31;
    if (w >= NN) return;
    int beg = g_rowptr[w], end = g_rowptr[w + 1];
    if (beg == end) return;
    int h = lane & 7, es = lane >> 3;
    float ad = g_ad1[w * NHEADS + h];
    float mx = -INFINITY;
    for (int j = beg + es; j < end; j += 4) {
        int s = g_csrc[j];
        float v = lrelu(g_as1[s * NHEADS + h] + ad);
        mx = fmaxf(mx, v);
    }
    mx = fmaxf(mx, __shfl_xor_sync(0xFFFFFFFFu, mx, 8));
    mx = fmaxf(mx, __shfl_xor_sync(0xFFFFFFFFu, mx, 16));
    float den = 0.f;
    for (int j = beg + es; j < end; j += 4) {
        int s = g_csrc[j];
        float v = lrelu(g_as1[s * NHEADS + h] + ad);
        den += __expf(v - mx);
    }
    den += __shfl_xor_sync(0xFFFFFFFFu, den, 8);
    den += __shfl_xor_sync(0xFFFFFFFFu, den, 16);
    float inv = 1.f / fmaxf(den, 1e-16f);
    for (int j = beg + es; j < end; j += 4) {
        int s = g_csrc[j];
        float v = lrelu(g_as1[s * NHEADS + h] + ad);
        g_alpha1[(size_t)j * NHEADS + h] = __expf(v - mx) * inv;
    }
}

__global__ void k_softmax2() {
    int gt = blockIdx.x * blockDim.x + threadIdx.x;
    int w = gt >> 5, lane = gt & 31;
    if (w >= NN) return;
    int beg = g_rowptr[w], end = g_rowptr[w + 1];
    if (beg == end) return;
    float ad = g_ad2[w];
    float mx = -INFINITY;
    for (int j = beg + lane; j < end; j += 32) {
        float v = lrelu(g_as2[g_csrc[j]] + ad);
        mx = fmaxf(mx, v);
    }
#pragma unroll
    for (int off = 16; off; off >>= 1) mx = fmaxf(mx, __shfl_xor_sync(0xFFFFFFFFu, mx, off));
    float den = 0.f;
    for (int j = beg + lane; j < end; j += 32) {
        float v = lrelu(g_as2[g_csrc[j]] + ad);
        den += __expf(v - mx);
    }
#pragma unroll
    for (int off = 16; off; off >>= 1) den += __shfl_xor_sync(0xFFFFFFFFu, den, off);
    float inv = 1.f / fmaxf(den, 1e-16f);
    for (int j = beg + lane; j < end; j += 32) {
        float v = lrelu(g_as2[g_csrc[j]] + ad);
        g_alpha2[j] = __expf(v - mx) * inv;
    }
}

// ---------------- aggregation ----------------
__global__ void k_agg1(const float* __restrict__ bias1) {
    int gt = blockIdx.x * blockDim.x + threadIdx.x;
    int w = gt >> 5, lane = gt & 31;
    if (w >= NN) return;
    int beg = g_rowptr[w], end = g_rowptr[w + 1];
    int hh = lane >> 2;
    float ax = 0.f, ay = 0.f, az = 0.f, aw = 0.f;
#pragma unroll 2
    for (int j = beg; j < end; j++) {
        int s = g_csrc[j];
        float a = g_alpha1[(size_t)j * NHEADS + hh];
        float4 t4 = *reinterpret_cast<const float4*>(g_t1 + (size_t)s * HD + lane * 4);
        ax += a * t4.x; ay += a * t4.y; az += a * t4.z; aw += a * t4.w;
    }
    float4 b4 = *reinterpret_cast<const float4*>(bias1 + lane * 4);
    float4 o;
    o.x = lrelu(ax + b4.x); o.y = lrelu(ay + b4.y);
    o.z = lrelu(az + b4.z); o.w = lrelu(aw + b4.w);
    *reinterpret_cast<float4*>(g_out1 + (size_t)w * HD + lane * 4) = o;
}

__global__ void k_agg2(const float* __restrict__ bias2) {
    int gt = blockIdx.x * blockDim.x + threadIdx.x;
    int w = gt >> 5, lane = gt & 31;
    if (w >= NN) return;
    int beg = g_rowptr[w], end = g_rowptr[w + 1];
    float ax = 0.f, ay = 0.f, az = 0.f, aw = 0.f;
#pragma unroll 2
    for (int j = beg; j < end; j++) {
        int s = g_csrc[j];
        float a = g_alpha2[j];
        float4 t4 = *reinterpret_cast<const float4*>(g_t2 + (size_t)s * HD + lane * 4);
        ax += a * t4.x; ay += a * t4.y; az += a * t4.z; aw += a * t4.w;
    }
    float4 b4 = *reinterpret_cast<const float4*>(bias2 + lane * 4);
    float4 o = make_float4(ax + b4.x, ay + b4.y, az + b4.z, aw + b4.w);
    *reinterpret_cast<float4*>(g_conv2 + (size_t)w * HD + lane * 4) = o;
}

// ---------------- final: BN2 apply + row L2 normalize ----------------
__global__ void k_final(float* __restrict__ out) {
    int gt = blockIdx.x * blockDim.x + threadIdx.x;
    int w = gt >> 5, lane = gt & 31;
    if (w >= NN) return;
    float4 h4 = *reinterpret_cast<const float4*>(g_h2 + (size_t)w * HD + lane * 4);
    float4 s4 = *reinterpret_cast<const float4*>(g_s2 + lane * 4);
    float4 sh4 = *reinterpret_cast<const float4*>(g_sh2 + lane * 4);
    float4 y;
    y.x = h4.x * s4.x + sh4.x; y.y = h4.y * s4.y + sh4.y;
    y.z = h4.z * s4.z + sh4.z; y.w = h4.w * s4.w + sh4.w;
    float ss = y.x * y.x + y.y * y.y + y.z * y.z + y.w * y.w;
#pragma unroll
    for (int off = 16; off; off >>= 1) ss += __shfl_xor_sync(0xFFFFFFFFu, ss, off);
    float inv = 1.f / fmaxf(sqrtf(ss), 1e-12f);
    y.x *= inv; y.y *= inv; y.z *= inv; y.w *= inv;
    *reinterpret_cast<float4*>(out + (size_t)w * HD + lane * 4) = y;
}

// ---------------- host launcher ----------------
extern "C" void kernel_launch(void* const* d_in, const int* in_sizes, int n_in,
                              void* d_out, int out_size) {
    const float* x        = (const float*)d_in[0];
    const float* W_in     = (const float*)d_in[1];
    const float* b_in     = (const float*)d_in[2];
    const float* gamma1   = (const float*)d_in[3];
    const float* beta1    = (const float*)d_in[4];
    const float* W1       = (const float*)d_in[5];
    const float* att_src1 = (const float*)d_in[6];
    const float* att_dst1 = (const float*)d_in[7];
    const float* bias1    = (const float*)d_in[8];
    const float* W2       = (const float*)d_in[9];
    const float* att_src2 = (const float*)d_in[10];
    const float* att_dst2 = (const float*)d_in[11];
    const float* bias2    = (const float*)d_in[12];
    const float* W_skip   = (const float*)d_in[13];
    const float* b_skip   = (const float*)d_in[14];
    const float* gamma2   = (const float*)d_in[15];
    const float* beta2    = (const float*)d_in[16];
    const void*  ei       = (const void*)d_in[17];
    float* out = (float*)d_out;

    float *p_h0, *p_t1, *p_out1, *p_t2, *p_conv2, *p_h2, *p_W1p, *p_c1;
    float *p_bnsum1, *p_bnsq1, *p_bnsum2, *p_bnsq2;
    cudaGetSymbolAddress((void**)&p_h0, g_h0);
    cudaGetSymbolAddress((void**)&p_t1, g_t1);
    cudaGetSymbolAddress((void**)&p_out1, g_out1);
    cudaGetSymbolAddress((void**)&p_t2, g_t2);
    cudaGetSymbolAddress((void**)&p_conv2, g_conv2);
    cudaGetSymbolAddress((void**)&p_h2, g_h2);
    cudaGetSymbolAddress((void**)&p_W1p, g_W1p);
    cudaGetSymbolAddress((void**)&p_c1, g_c1);
    cudaGetSymbolAddress((void**)&p_bnsum1, g_bnsum1);
    cudaGetSymbolAddress((void**)&p_bnsq1, g_bnsq1);
    cudaGetSymbolAddress((void**)&p_bnsum2, g_bnsum2);
    cudaGetSymbolAddress((void**)&p_bnsq2, g_bnsq2);

    const int nb_edge = (EE + 255) / 256;
    const int nb_node = (NN * 32 + 255) / 256;
    const int gemm_grid = (NN + 127) / 128;

    k_detect<<<1, 1>>>(ei);
    k_zero<<<(NN + 255) / 256, 256>>>();
    k_count<<<nb_edge, 256>>>(ei);
    k_scanA<<<NSCAN, SCAN_BLK>>>();
    k_scanB<<<1, SCAN_BLK>>>();
    k_scanC<<<NSCAN, SCAN_BLK>>>();
    k_fill<<<nb_edge, 256>>>(ei);

    // h0 = leaky(x @ W_in + b_in), BN1 stats
    k_gemm<IND, true, false, true><<<gemm_grid, 256>>>(x, W_in, p_h0, b_in, nullptr, p_bnsum1, p_bnsq1);
    k_bnprep1<<<1, HD>>>(gamma1, beta1, W1);
    // t1 = h_norm @ W1  (BN folded)
    k_gemm<HD, false, false, false><<<gemm_grid, 256>>>(p_h0, p_W1p, p_t1, p_c1, nullptr, nullptr, nullptr);
    k_att1<<<nb_node, 256>>>(att_src1, att_dst1);
    k_softmax1<<<nb_node, 256>>>();
    k_agg1<<<nb_node, 256>>>(bias1);
    // t2 = out1 @ W2
    k_gemm<HD, false, false, false><<<gemm_grid, 256>>>(p_out1, W2, p_t2, nullptr, nullptr, nullptr, nullptr);
    k_att2<<<nb_node, 256>>>(att_src2, att_dst2);
    k_softmax2<<<nb_node, 256>>>();
    k_agg2<<<nb_node, 256>>>(bias2);
    // h2 = conv2 + out1 @ W_skip + b_skip, BN2 stats
    k_gemm<HD, false, true, true><<<gemm_grid, 256>>>(p_out1, W_skip, p_h2, b_skip, p_conv2, p_bnsum2, p_bnsq2);
    k_bnprep2<<<1, HD>>>(gamma2, beta2);
    k_final<<<nb_node, 256>>>(out);
}